// round 11
// baseline (speedup 1.0000x reference)
#include <cuda_runtime.h>
#include <math_constants.h>

// Problem constants (dataset-fixed): N = 262144 rows, C = 1000 classes.
#define CE_MAXCTAS 65536   // >= ceil(N/8) for the benched shape (32768)
#define CE_NPART   64

__device__ float g_cta_loss[CE_MAXCTAS];
__device__ float g_partials[CE_NPART];

// ---------------------------------------------------------------------------
// Specialized kernel for C == 1000: ONE WARP per row, 8 rows per CTA.
// Lane l owns cols {k*128 + l*4 .. +3}, k = 0..7 (compile-time bounds for
// C=1000). All 8 LDG.128 front-batched (MLP=8), evict-first (.cs). Label
// logit extracted from registers (SEL chain + shfl) — no gather load.
// Epilogue: per-CTA block sum of 8 row losses.  (UNCHANGED from R8 — 91% HBM)
// ---------------------------------------------------------------------------
__global__ __launch_bounds__(256, 4)
void ce_warp_c1000_kernel(const float* __restrict__ logits,
                          const long long* __restrict__ labels,
                          int N)
{
    const int lane = threadIdx.x & 31;
    const int warp = threadIdx.x >> 5;
    const int row  = (blockIdx.x << 3) + warp;   // 8 warps per CTA

    __shared__ float sh[8];

    float rowloss = 0.0f;
    if (row < N) {
        const float* rowp = logits + (long long)row * 1000LL;

        const int lab = (int)labels[row];

        float4 v[8];
        #pragma unroll
        for (int k = 0; k < 7; ++k)
            v[k] = __ldcs(reinterpret_cast<const float4*>(rowp + (k << 7) + (lane << 2)));
        if (lane < 26)
            v[7] = __ldcs(reinterpret_cast<const float4*>(rowp + 896 + (lane << 2)));
        else
            v[7] = make_float4(-CUDART_INF_F, -CUDART_INF_F,
                               -CUDART_INF_F, -CUDART_INF_F);

        const int klab = lab >> 7;
        const int elab = lab & 3;
        const int slab = (lab >> 2) & 31;
        float4 w = v[0];
        #pragma unroll
        for (int k = 1; k < 8; ++k)
            if (klab == k) w = v[k];
        float val = (elab == 0) ? w.x : (elab == 1) ? w.y : (elab == 2) ? w.z : w.w;
        const float xlab = __shfl_sync(0xffffffffu, val, slab);

        float m = -CUDART_INF_F;
        #pragma unroll
        for (int k = 0; k < 8; ++k)
            m = fmaxf(m, fmaxf(fmaxf(v[k].x, v[k].y), fmaxf(v[k].z, v[k].w)));
        #pragma unroll
        for (int off = 16; off > 0; off >>= 1)
            m = fmaxf(m, __shfl_xor_sync(0xffffffffu, m, off));

        float s = 0.0f;
        #pragma unroll
        for (int k = 0; k < 8; ++k)
            s += __expf(v[k].x - m) + __expf(v[k].y - m)
               + __expf(v[k].z - m) + __expf(v[k].w - m);
        #pragma unroll
        for (int off = 16; off > 0; off >>= 1)
            s += __shfl_xor_sync(0xffffffffu, s, off);

        rowloss = __logf(s) + m - xlab;          // positive loss = -logp[label]
    }

    if (lane == 0) sh[warp] = rowloss;
    __syncthreads();
    if (threadIdx.x == 0) {
        float c = 0.0f;
        #pragma unroll
        for (int k = 0; k < 8; ++k) c += sh[k];
        g_cta_loss[blockIdx.x] = c;
    }
}

// ---------------------------------------------------------------------------
// Generic fallback (any C): warp per row, online softmax, scalar loads.
// Same per-CTA-sum epilogue. Correctness-only path.
// ---------------------------------------------------------------------------
__global__ __launch_bounds__(256)
void ce_warp_generic_kernel(const float* __restrict__ logits,
                            const long long* __restrict__ labels,
                            int C, int N)
{
    const int lane = threadIdx.x & 31;
    const int warp = threadIdx.x >> 5;
    const int row  = (blockIdx.x << 3) + warp;

    __shared__ float sh[8];

    float rowloss = 0.0f;
    if (row < N) {
        const float* rowp = logits + (long long)row * (long long)C;
        const int lab = (int)labels[row];

        float m = -CUDART_INF_F, s = 0.0f;
        for (int col = lane; col < C; col += 32) {
            const float x = rowp[col];
            const float mn = fmaxf(m, x);
            s = s * __expf(m - mn) + __expf(x - mn);
            m = mn;
        }
        #pragma unroll
        for (int off = 16; off > 0; off >>= 1) {
            const float mo = __shfl_xor_sync(0xffffffffu, m, off);
            const float so = __shfl_xor_sync(0xffffffffu, s, off);
            const float mn = fmaxf(m, mo);
            s = s * __expf(m - mn) + so * __expf(mo - mn);
            m = mn;
        }
        float xlab = 0.0f;
        if (lane == 0) xlab = rowp[lab];
        rowloss = __logf(s) + m - xlab;          // valid in lane 0
    }

    if (lane == 0) sh[warp] = rowloss;
    __syncthreads();
    if (threadIdx.x == 0) {
        float c = 0.0f;
        #pragma unroll
        for (int k = 0; k < 8; ++k) c += sh[k];
        g_cta_loss[blockIdx.x] = c;
    }
}

// ---------------------------------------------------------------------------
// Stage-1 reduce: 64 CTAs x 256 threads, grid-stride over nCTA per-CTA sums.
// For the benched shape each CTA folds 512 floats (128 LDG.128 total) -> one
// DRAM/L2 latency round per CTA, spread across 64 SMs.
// ---------------------------------------------------------------------------
__global__ __launch_bounds__(256)
void ce_reduce1_kernel(int nCTA)
{
    const int tid = threadIdx.x;
    float s = 0.0f;

    const int nvec = nCTA >> 2;
    const float4* p4 = reinterpret_cast<const float4*>(g_cta_loss);
    for (int i = blockIdx.x * 256 + tid; i < nvec; i += CE_NPART * 256) {
        const float4 u = p4[i];
        s += (u.x + u.y) + (u.z + u.w);
    }
    if (blockIdx.x == 0)                          // scalar remainder (none for benched shape)
        for (int i = (nvec << 2) + tid; i < nCTA; i += 256)
            s += g_cta_loss[i];

    // block sum (256 threads)
    __shared__ float sh[8];
    const int lane = tid & 31;
    const int warp = tid >> 5;
    #pragma unroll
    for (int off = 16; off > 0; off >>= 1)
        s += __shfl_xor_sync(0xffffffffu, s, off);
    if (lane == 0) sh[warp] = s;
    __syncthreads();
    if (tid < 8) {
        float r = sh[tid];
        #pragma unroll
        for (int off = 4; off > 0; off >>= 1)
            r += __shfl_xor_sync(0x000000ffu, r, off);
        if (tid == 0) g_partials[blockIdx.x] = r;
    }
}

// ---------------------------------------------------------------------------
// Stage-2 reduce: two warps fold 64 partials -> out = sum / N.
// ---------------------------------------------------------------------------
__global__ __launch_bounds__(64)
void ce_reduce2_kernel(float* __restrict__ out, int N)
{
    const int tid  = threadIdx.x;
    const int lane = tid & 31;
    float s = g_partials[tid];

    __shared__ float sh[2];
    #pragma unroll
    for (int off = 16; off > 0; off >>= 1)
        s += __shfl_xor_sync(0xffffffffu, s, off);
    if (lane == 0) sh[tid >> 5] = s;
    __syncthreads();
    if (tid == 0) out[0] = (sh[0] + sh[1]) / (float)N;
}

// ---------------------------------------------------------------------------
extern "C" void kernel_launch(void* const* d_in, const int* in_sizes, int n_in,
                              void* d_out, int out_size)
{
    const float*     logits = (const float*)d_in[0];
    const long long* labels = (const long long*)d_in[1];
    float*           out    = (float*)d_out;

    const int N = in_sizes[1];                 // 262144
    const int C = in_sizes[0] / N;             // 1000

    const int grid = (N + 7) / 8;              // 8 warps (rows) per CTA

    if (C == 1000)
        ce_warp_c1000_kernel<<<grid, 256>>>(logits, labels, N);
    else
        ce_warp_generic_kernel<<<grid, 256>>>(logits, labels, C, N);

    ce_reduce1_kernel<<<CE_NPART, 256>>>(grid);
    ce_reduce2_kernel<<<1, 64>>>(out, N);
}